// round 16
// baseline (speedup 1.0000x reference)
#include <cuda_runtime.h>
#include <cuda_fp16.h>
#include <math.h>

typedef unsigned int       u32;
typedef unsigned short     u16;
typedef unsigned long long u64;

#define BATCH 8
#define CIN   64
#define COUT  128
#define HH    128
#define WW    128

// ---------------- device globals ----------------
// Even/odd split constant matrices, single fp16 plane, packed [row][col/2] u32 (64x32).
__device__ u32 g_De[2048], g_Do[2048];     // De[k'][h'] = D[2k'][h'], Do = D[2k'+1][h']
__device__ u32 g_Me[2048], g_Mo[2048];     // Me[n'][k'] = 256*M[n'][2k'], Mo = 256*M[n'][2k'+1]
__device__ float g_D5[640];                // first 5 cols of D (fp32, for wtrans)
__device__ u32 g_wd[128*5*4096];           // x64 [k][j] tiles of [o][c/2], single fp16 plane
__device__ u32 g_xd16[BATCH*CIN*HH*64];    // [b][c][k][w/2] single fp16 plane
__device__ u32 g_y16 [BATCH*COUT*HH*64];   // [b][o][k][w/2]

// ---------------- helpers ----------------
__device__ __forceinline__ u32 smem_u32(const void* p) {
    u32 a; asm("{ .reg .u64 t; cvta.to.shared.u64 t, %1; cvt.u32.u64 %0, t; }" : "=r"(a) : "l"(p));
    return a;
}
__device__ __forceinline__ void cp16(u32 dst, const void* src) {
    asm volatile("cp.async.cg.shared.global [%0], [%1], 16;" :: "r"(dst), "l"(src) : "memory");
}
#define CP_COMMIT() asm volatile("cp.async.commit_group;" ::: "memory")
#define CP_WAIT(n)  asm volatile("cp.async.wait_group %0;" :: "n"(n) : "memory")

__device__ __forceinline__ void ldsm_x4(u32& r0, u32& r1, u32& r2, u32& r3, u32 addr) {
    asm volatile("ldmatrix.sync.aligned.m8n8.x4.shared.b16 {%0,%1,%2,%3}, [%4];"
        : "=r"(r0), "=r"(r1), "=r"(r2), "=r"(r3) : "r"(addr) : "memory");
}
__device__ __forceinline__ void ldsm_x4t(u32& r0, u32& r1, u32& r2, u32& r3, u32 addr) {
    asm volatile("ldmatrix.sync.aligned.m8n8.x4.trans.shared.b16 {%0,%1,%2,%3}, [%4];"
        : "=r"(r0), "=r"(r1), "=r"(r2), "=r"(r3) : "r"(addr) : "memory");
}
__device__ __forceinline__ void mma_f16(float* c, const u32* a, u32 b0, u32 b1) {
    asm volatile("mma.sync.aligned.m16n8k16.row.col.f32.f16.f16.f32 "
        "{%0,%1,%2,%3}, {%4,%5,%6,%7}, {%8,%9}, {%0,%1,%2,%3};"
        : "+f"(c[0]), "+f"(c[1]), "+f"(c[2]), "+f"(c[3])
        : "r"(a[0]), "r"(a[1]), "r"(a[2]), "r"(a[3]), "r"(b0), "r"(b1));
}
__device__ __forceinline__ u16 f2h(float v) { return __half_as_ushort(__float2half_rn(v)); }

// ---------------- constants ----------------
__global__ void k_consts() {
    int idx = blockIdx.x * blockDim.x + threadIdx.x;
    if (idx < 640) {
        int k = idx / 5, h = idx % 5;
        g_D5[idx] = (float)(2.0 * cos(M_PI * (2.0*h + 1.0) * k / 256.0));
    }
    if (idx >= 2048) return;
    int r = idx >> 5, cp = idx & 31;
    int c0 = 2*cp, c1 = 2*cp + 1;
    float de0 = (float)(2.0 * cos(M_PI * (2.0*c0 + 1.0) * (2.0*r) / 256.0));
    float de1 = (float)(2.0 * cos(M_PI * (2.0*c1 + 1.0) * (2.0*r) / 256.0));
    g_De[idx] = (u32)f2h(de0) | ((u32)f2h(de1) << 16);
    float do0 = (float)(2.0 * cos(M_PI * (2.0*c0 + 1.0) * (2.0*r + 1.0) / 256.0));
    float do1 = (float)(2.0 * cos(M_PI * (2.0*c1 + 1.0) * (2.0*r + 1.0) / 256.0));
    g_Do[idx] = (u32)f2h(do0) | ((u32)f2h(do1) << 16);
    float me0 = (float)(cos(M_PI * (2.0*r + 1.0) * (2.0*c0) / 256.0) * ((c0 == 0) ? 0.5 : 1.0));
    float me1 = (float)(cos(M_PI * (2.0*r + 1.0) * (2.0*c1) / 256.0));
    g_Me[idx] = (u32)f2h(me0) | ((u32)f2h(me1) << 16);
    float mo0 = (float)(cos(M_PI * (2.0*r + 1.0) * (2.0*c0 + 1.0) / 256.0));
    float mo1 = (float)(cos(M_PI * (2.0*r + 1.0) * (2.0*c1 + 1.0) / 256.0));
    g_Mo[idx] = (u32)f2h(mo0) | ((u32)f2h(mo1) << 16);
}

// ---------------- weight transform: wd[k][j][o][c] = 64 * sum_h D[k,h]*W[o,c,h,j] ----------------
__global__ void k_wtrans(const float* __restrict__ wgt) {
    __shared__ float sw[5*64];
    int j = blockIdx.x >> 7, o = blockIdx.x & 127;
    int tid = threadIdx.x;
    for (int i = tid; i < 320; i += 256) {
        int h = i >> 6, c = i & 63;
        sw[h*64 + c] = wgt[((o*64 + c)*5 + h)*5 + j];
    }
    __syncthreads();
    for (int i = tid; i < 4096; i += 256) {
        int k = i >> 5, cp = i & 31;
        float a0 = 0.f, a1 = 0.f;
#pragma unroll
        for (int h = 0; h < 5; h++) {
            float d = g_D5[k*5 + h];
            a0 = fmaf(d, sw[h*64 + 2*cp],     a0);
            a1 = fmaf(d, sw[h*64 + 2*cp + 1], a1);
        }
        g_wd[(u32)(k*5 + j)*4096 + o*32 + cp] =
            (u32)f2h(64.f * a0) | ((u32)f2h(64.f * a1) << 16);
    }
}

// ---------------- stage 1 (DCT, even/odd): two 64x128x64 GEMMs per slice ----------------
// A planes: De/Do, 64 rows x 64 fp16, stride 144 (9216 B each).
// B tiles: Bs (x[h]+x[127-h]) and Bd (diff), 64 rows x 128 fp16, stride 272 (17408 B each).
#define TSA6 144
#define TSB2 272
__global__ __launch_bounds__(256, 2)
void k_dct_mma(const float* __restrict__ xsrc) {
    extern __shared__ __align__(16) char sm[];
    const u32 OFF_BS = 18432, OFF_BD = 35840;   // total 53248
    u32 sb = smem_u32(sm);
    int tid = threadIdx.x, wid = tid >> 5, lane = tid & 31;

    int m0 = (wid >> 1) * 16, n0 = (wid & 1) * 64;
    int rowA = lane & 15;
    int kA = (lane & 16) ? 8 : 0;
    int rowK = lane & 15;
    int ntAdd = (lane & 16) ? 8 : 0;

    // A planes via cp.async
    for (int i = tid; i < 1024; i += 256) {
        int p = i >> 9, ii = i & 511;
        int r = ii >> 3, ch = ii & 7;
        cp16(sb + p*9216 + r*TSA6 + ch*16, (p ? g_Do : g_De) + r*32 + ch*4);
    }
    CP_COMMIT();
    // B build: direct LDG of x rows h and 127-h, sum/diff in fp32, convert fp16
    const float* xb = xsrc + (size_t)blockIdx.x * 16384;
    for (int i = tid; i < 2048; i += 256) {
        int h = i >> 5, w4 = i & 31;
        float4 a = ((const float4*)(xb + h*128))[w4];
        float4 b = ((const float4*)(xb + (127 - h)*128))[w4];
        u32 s0 = (u32)f2h(a.x + b.x) | ((u32)f2h(a.y + b.y) << 16);
        u32 s1 = (u32)f2h(a.z + b.z) | ((u32)f2h(a.w + b.w) << 16);
        u32 d0 = (u32)f2h(a.x - b.x) | ((u32)f2h(a.y - b.y) << 16);
        u32 d1 = (u32)f2h(a.z - b.z) | ((u32)f2h(a.w - b.w) << 16);
        *(uint2*)(sm + OFF_BS + h*TSB2 + w4*8) = make_uint2(s0, s1);
        *(uint2*)(sm + OFF_BD + h*TSB2 + w4*8) = make_uint2(d0, d1);
    }
    CP_WAIT(0);
    __syncthreads();

    float accE[8][4], accO[8][4];
#pragma unroll
    for (int nt = 0; nt < 8; nt++)
#pragma unroll
        for (int q = 0; q < 4; q++) { accE[nt][q] = 0.f; accO[nt][q] = 0.f; }

#pragma unroll
    for (int ks = 0; ks < 4; ks++) {
        int k0 = ks * 16;
        u32 ae[4], ao[4];
        u32 base = (u32)((m0 + rowA) * TSA6 + (k0 + kA) * 2);
        ldsm_x4(ae[0], ae[1], ae[2], ae[3], sb + 0    + base);
        ldsm_x4(ao[0], ao[1], ao[2], ao[3], sb + 9216 + base);
        u32 rbase = (u32)((k0 + rowK) * TSB2);
#pragma unroll
        for (int nt = 0; nt < 8; nt += 2) {
            u32 off = rbase + (u32)((n0 + nt*8 + ntAdd) * 2);
            u32 bs[4], bd[4];
            ldsm_x4t(bs[0], bs[1], bs[2], bs[3], sb + OFF_BS + off);
            ldsm_x4t(bd[0], bd[1], bd[2], bd[3], sb + OFF_BD + off);
#pragma unroll
            for (int q = 0; q < 2; q++) {
                mma_f16(accE[nt + q], ae, bs[2*q], bs[2*q + 1]);
                mma_f16(accO[nt + q], ao, bd[2*q], bd[2*q + 1]);
            }
        }
    }

    // epilogue: direct packed stores. E -> even k rows, O -> odd k rows.
    u32* od = g_xd16 + (size_t)blockIdx.x * 8192;
    int r = m0 + (lane >> 2);
#pragma unroll
    for (int nt = 0; nt < 8; nt++) {
        int c2 = (n0 + nt*8)/2 + (lane & 3);
        od[(2*r)*64      + c2] = (u32)f2h(accE[nt][0]) | ((u32)f2h(accE[nt][1]) << 16);
        od[(2*r + 1)*64  + c2] = (u32)f2h(accO[nt][0]) | ((u32)f2h(accO[nt][1]) << 16);
        od[(2*r + 16)*64 + c2] = (u32)f2h(accE[nt][2]) | ((u32)f2h(accE[nt][3]) << 16);
        od[(2*r + 17)*64 + c2] = (u32)f2h(accO[nt][2]) | ((u32)f2h(accO[nt][3]) << 16);
    }
}

// ---------------- stage 4 (iDCT, even/odd): E/O butterfly, 2 slices/CTA ----------------
// A planes: Me/Mo 64x64 fp16 stride 144. B stage s: y_even / y_odd tiles (17408 each).
__global__ __launch_bounds__(256, 2)
void k_idct_mma(const float* __restrict__ bias, float* __restrict__ outp) {
    extern __shared__ __align__(16) char sm[];
    const u32 OFF_B = 18432;   // stage s: OFF_B + s*34816; even +0, odd +17408. total 88064.
    u32 sb = smem_u32(sm);
    int tid = threadIdx.x, wid = tid >> 5, lane = tid & 31;

    int m0 = (wid >> 1) * 16, n0 = (wid & 1) * 64;
    int rowA = lane & 15;
    int kA = (lane & 16) ? 8 : 0;
    int rowK = lane & 15;
    int ntAdd = (lane & 16) ? 8 : 0;

    size_t slice0 = (size_t)blockIdx.x * 2;

    auto load_b = [&](int sl, int s) {
        const u32* ys = g_y16 + (slice0 + sl) * 8192;
        u32 bBase = sb + OFF_B + s*34816;
        for (int i = tid; i < 2048; i += 256) {
            int t = i >> 10, ii = i & 1023;
            int r = ii >> 4, ch = ii & 15;
            cp16(bBase + t*17408 + r*TSB2 + ch*16, ys + (size_t)(2*r + t)*64 + ch*4);
        }
        CP_COMMIT();
    };

    // A planes
    for (int i = tid; i < 1024; i += 256) {
        int p = i >> 9, ii = i & 511;
        int r = ii >> 3, ch = ii & 7;
        cp16(sb + p*9216 + r*TSA6 + ch*16, (p ? g_Mo : g_Me) + r*32 + ch*4);
    }
    CP_COMMIT();
    load_b(0, 0);
    CP_WAIT(0);
    __syncthreads();
    load_b(1, 1);

#pragma unroll
    for (int sl = 0; sl < 2; sl++) {
        u32 bBase = sb + OFF_B + sl*34816;
        float accE[8][4], accO[8][4];
#pragma unroll
        for (int nt = 0; nt < 8; nt++)
#pragma unroll
            for (int q = 0; q < 4; q++) { accE[nt][q] = 0.f; accO[nt][q] = 0.f; }

#pragma unroll
        for (int ks = 0; ks < 4; ks++) {
            int k0 = ks * 16;
            u32 ae[4], ao[4];
            u32 base = (u32)((m0 + rowA) * TSA6 + (k0 + kA) * 2);
            ldsm_x4(ae[0], ae[1], ae[2], ae[3], sb + 0    + base);
            ldsm_x4(ao[0], ao[1], ao[2], ao[3], sb + 9216 + base);
            u32 rbase = (u32)((k0 + rowK) * TSB2);
#pragma unroll
            for (int nt = 0; nt < 8; nt += 2) {
                u32 off = rbase + (u32)((n0 + nt*8 + ntAdd) * 2);
                u32 be[4], bo[4];
                ldsm_x4t(be[0], be[1], be[2], be[3], bBase + off);
                ldsm_x4t(bo[0], bo[1], bo[2], bo[3], bBase + 17408 + off);
#pragma unroll
                for (int q = 0; q < 2; q++) {
                    mma_f16(accE[nt + q], ae, be[2*q], be[2*q + 1]);
                    mma_f16(accO[nt + q], ao, bo[2*q], bo[2*q + 1]);
                }
            }
        }

        // epilogue: butterfly out[n] = E+O, out[127-n] = E-O
        {
            size_t o = slice0 + sl;
            float bv = bias[o & 127];
            const float is = 1.f / 256.f;
            float* op = outp + o * 16384;
            int n1 = m0 + (lane >> 2);
#pragma unroll
            for (int nt = 0; nt < 8; nt++) {
                int c = n0 + nt*8 + 2*(lane & 3);
                float e0 = accE[nt][0]*is, e1 = accE[nt][1]*is;
                float o0 = accO[nt][0]*is, o1 = accO[nt][1]*is;
                float e2 = accE[nt][2]*is, e3 = accE[nt][3]*is;
                float o2 = accO[nt][2]*is, o3 = accO[nt][3]*is;
                *(float2*)(op + n1*128 + c)         = make_float2(e0 + o0 + bv, e1 + o1 + bv);
                *(float2*)(op + (127 - n1)*128 + c) = make_float2(e0 - o0 + bv, e1 - o1 + bv);
                *(float2*)(op + (n1 + 8)*128 + c)   = make_float2(e2 + o2 + bv, e3 + o3 + bv);
                *(float2*)(op + (119 - n1)*128 + c) = make_float2(e2 - o2 + bv, e3 - o3 + bv);
            }
        }
        if (sl == 0) { CP_WAIT(0); __syncthreads(); }
    }
}

// ---------------- stage 3: per (b,k): y = (wd64 conv xd)/64, single-plane A -------------
#define TS3 144
__global__ __launch_bounds__(256, 2)
void k_conv_mma() {
    extern __shared__ __align__(16) char sm[];
    const u32 OFF_B = 0, OFF_A0 = 18432, OFF_A1 = 36864;   // pipeline 55296; epilogue needs 66048
    u32 sb = smem_u32(sm);
    int tid = threadIdx.x, wid = tid >> 5, lane = tid & 31;
    int blk = blockIdx.x, b = blk >> 7, k = blk & 127;

    // 1. cp.async X slice (16 KB) into A1 region
    for (int i = tid; i < 1024; i += 256) {
        int c = i >> 4, ch = i & 15;
        size_t gi = ((size_t)(b*64 + c)*128 + k)*64 + ch*4;
        cp16(sb + OFF_A1 + i*16, g_xd16 + gi);
    }
    CP_COMMIT();
    // 2. cp.async A_0 into buf0
    {
        size_t wbase = (size_t)(k*5 + 0) * 4096;
        for (int i = tid; i < 1024; i += 256) {
            int o = i >> 3, ch = i & 7;
            cp16(sb + OFF_A0 + o*TS3 + ch*16, g_wd + wbase + o*32 + ch*4);
        }
        CP_COMMIT();
    }
    CP_WAIT(1);
    __syncthreads();
    // 3. build B[w][c] once from X
    {
        const u16* sh = (const u16*)(sm + OFF_A1);
        u32* dB = (u32*)(sm + OFF_B);
        for (int i = tid; i < 4096; i += 256) {
            int w = i & 127, cp = i >> 7;
            dB[w*36 + cp] = (u32)sh[(2*cp)*128 + w] | ((u32)sh[(2*cp + 1)*128 + w] << 16);
        }
    }
    CP_WAIT(0);
    __syncthreads();

    int m0 = (wid >> 1) * 32, n0 = (wid & 1) * 64;
    int rowA = lane & 15;
    int kA = (lane & 16) ? 8 : 0;
    int rowB = lane & 7;
    int kB = (lane & 8) ? 8 : 0;
    int ntAdd = (lane & 16) ? 8 : 0;

    float acc[2][8][4];
#pragma unroll
    for (int mt = 0; mt < 2; mt++)
#pragma unroll
        for (int nt = 0; nt < 8; nt++)
#pragma unroll
            for (int q = 0; q < 4; q++) acc[mt][nt][q] = 0.f;

#pragma unroll
    for (int j = 0; j < 5; j++) {
        if (j < 4) {
            size_t wbase = (size_t)(k*5 + j + 1) * 4096;
            u32 dst = sb + (((j + 1) & 1) ? OFF_A1 : OFF_A0);
            for (int i = tid; i < 1024; i += 256) {
                int o = i >> 3, ch = i & 7;
                cp16(dst + o*TS3 + ch*16, g_wd + wbase + o*32 + ch*4);
            }
            CP_COMMIT();
        }
        u32 aBase = sb + ((j & 1) ? OFF_A1 : OFF_A0);
#pragma unroll
        for (int ks = 0; ks < 4; ks++) {
            int k0 = ks * 16;
            u32 af[2][4];
#pragma unroll
            for (int mt = 0; mt < 2; mt++) {
                u32 base = (u32)((m0 + mt*16 + rowA) * TS3 + (k0 + kA) * 2);
                ldsm_x4(af[mt][0], af[mt][1], af[mt][2], af[mt][3], aBase + base);
            }
#pragma unroll
            for (int nt = 0; nt < 8; nt += 2) {
                int wr = ((n0 + nt*8 + ntAdd + rowB) - j) & 127;
                u32 base = (u32)(wr * TS3 + (k0 + kB) * 2);
                u32 bf[4];
                ldsm_x4(bf[0], bf[1], bf[2], bf[3], sb + OFF_B + base);
#pragma unroll
                for (int q = 0; q < 2; q++)
#pragma unroll
                    for (int mt = 0; mt < 2; mt++)
                        mma_f16(acc[mt][nt + q], af[mt], bf[2*q], bf[2*q + 1]);
            }
        }
        if (j < 4) { CP_WAIT(0); __syncthreads(); }
    }

    // epilogue through fp32 staging; store y = acc/64 as single fp16 plane
    __syncthreads();
    float* se = (float*)(sm);   // [128][129] = 66048
#pragma unroll
    for (int mt = 0; mt < 2; mt++)
#pragma unroll
        for (int nt = 0; nt < 8; nt++) {
            int r = m0 + mt*16 + (lane >> 2);
            int c = n0 + nt*8 + 2*(lane & 3);
            se[r*129 + c]           = acc[mt][nt][0];
            se[r*129 + c + 1]       = acc[mt][nt][1];
            se[(r + 8)*129 + c]     = acc[mt][nt][2];
            se[(r + 8)*129 + c + 1] = acc[mt][nt][3];
        }
    __syncthreads();
    const float is = 1.f / 64.f;
    for (int i = tid; i < 8192; i += 256) {
        int o = i >> 6, wp = i & 63;
        size_t gi = ((size_t)(b*128 + o))*8192 + (size_t)k*64 + wp;
        g_y16[gi] = (u32)f2h(se[o*129 + 2*wp] * is) | ((u32)f2h(se[o*129 + 2*wp + 1] * is) << 16);
    }
}

// ---------------- launch ----------------
extern "C" void kernel_launch(void* const* d_in, const int* in_sizes, int n_in,
                              void* d_out, int out_size) {
    const float* x    = (const float*)d_in[0];   // (8,64,128,128)
    const float* wgt  = (const float*)d_in[1];   // (128,64,5,5)
    const float* bias = (const float*)d_in[2];   // (128,)
    float* out = (float*)d_out;                  // (8,128,128,128)

    const int SMD = 53248;    // A 2x9216 + B 2x17408
    const int SMI = 88064;    // A 2x9216 + B 2x34816
    const int SM3 = 66560;    // max(pipeline 55296, epilogue 66048)
    cudaFuncSetAttribute(k_dct_mma,  cudaFuncAttributeMaxDynamicSharedMemorySize, SMD);
    cudaFuncSetAttribute(k_idct_mma, cudaFuncAttributeMaxDynamicSharedMemorySize, SMI);
    cudaFuncSetAttribute(k_conv_mma, cudaFuncAttributeMaxDynamicSharedMemorySize, SM3);

    k_consts  <<<32, 256>>>();
    k_wtrans  <<<640, 256>>>(wgt);
    k_dct_mma <<<BATCH*CIN,     256, SMD>>>(x);
    k_conv_mma<<<BATCH*HH,      256, SM3>>>();
    k_idct_mma<<<BATCH*COUT/2,  256, SMI>>>(bias, out);
}